// round 1
// baseline (speedup 1.0000x reference)
#include <cuda_runtime.h>
#include <math.h>

// Problem constants
#define BATCH   64
#define IN_D    256
#define MEM_D   128
#define NSLOT   4096

// -------- scratch (no allocations allowed) --------
__device__ float g_v [BATCH * MEM_D];   // x@W_write + b_write
__device__ float g_wq[BATCH * MEM_D];   // x@W_wq + b_wq
__device__ float g_rq[BATCH * MEM_D];   // x@W_rq + b_rq
__device__ float g_qv[BATCH];           // v . rq  per batch
__device__ float g_d1[BATCH * NSLOT];   // mem_n . wq
__device__ float g_d2[BATCH * NSLOT];   // mem_n . rq
__device__ float g_c [BATCH * NSLOT];   // rw_n * (1 - ww_n)
__device__ float g_s [BATCH];           // sum_n rw_n * ww_n
__device__ float g_ro[BATCH * MEM_D];   // accumulated read_out (pre s*v term)

__device__ __forceinline__ float warpSum(float v) {
#pragma unroll
    for (int o = 16; o; o >>= 1) v += __shfl_xor_sync(0xffffffffu, v, o);
    return v;
}
__device__ __forceinline__ float warpMax(float v) {
#pragma unroll
    for (int o = 16; o; o >>= 1) v = fmaxf(v, __shfl_xor_sync(0xffffffffu, v, o));
    return v;
}

// ---------------------------------------------------------------------------
// Kernel 1: projections v, wq, rq  (64x128, K=256) + qv = v.rq, zero g_ro
// grid 64, block 128
// ---------------------------------------------------------------------------
__global__ void proj_kernel(const float* __restrict__ x,
                            const float* __restrict__ Ww, const float* __restrict__ bw,
                            const float* __restrict__ Wq, const float* __restrict__ bq,
                            const float* __restrict__ Wr, const float* __restrict__ br) {
    const int b = blockIdx.x;
    const int t = threadIdx.x;                // 0..127
    __shared__ float sx[IN_D];
    sx[t]       = x[b * IN_D + t];
    sx[t + 128] = x[b * IN_D + t + 128];
    __syncthreads();

    float aV = bw[t], aQ = bq[t], aR = br[t];
#pragma unroll 8
    for (int k = 0; k < IN_D; k++) {
        const float xv = sx[k];
        aV = fmaf(xv, Ww[k * MEM_D + t], aV);
        aQ = fmaf(xv, Wq[k * MEM_D + t], aQ);
        aR = fmaf(xv, Wr[k * MEM_D + t], aR);
    }
    g_v [b * MEM_D + t] = aV;
    g_wq[b * MEM_D + t] = aQ;
    g_rq[b * MEM_D + t] = aR;
    g_ro[b * MEM_D + t] = 0.0f;

    // qv = sum_d v*rq
    float p = warpSum(aV * aR);
    __shared__ float sr[4];
    if ((t & 31) == 0) sr[t >> 5] = p;
    __syncthreads();
    if (t == 0) g_qv[b] = sr[0] + sr[1] + sr[2] + sr[3];
}

// ---------------------------------------------------------------------------
// Kernel 2 (pass 1 over memory): d1[b,n] = mem_n.wq, d2[b,n] = mem_n.rq
// Warp-per-row, 32 rows per warp. grid 1024, block 256 (8192 warps total).
// ---------------------------------------------------------------------------
__global__ void dots_kernel(const float* __restrict__ mem) {
    const int gw   = (blockIdx.x * blockDim.x + threadIdx.x) >> 5;
    const int lane = threadIdx.x & 31;
    const int b    = gw >> 7;            // 128 warps per batch
    const int n0   = (gw & 127) << 5;    // 32 consecutive rows per warp

    const float4 wq4 = reinterpret_cast<const float4*>(g_wq + b * MEM_D)[lane];
    const float4 rq4 = reinterpret_cast<const float4*>(g_rq + b * MEM_D)[lane];

    const float4* mrow = reinterpret_cast<const float4*>(
        mem + ((size_t)b * NSLOT + n0) * MEM_D);
    float* o1 = g_d1 + b * NSLOT + n0;
    float* o2 = g_d2 + b * NSLOT + n0;

#pragma unroll 4
    for (int r = 0; r < 32; r++) {
        const float4 m = mrow[(size_t)r * 32 + lane];
        float a = m.x * wq4.x + m.y * wq4.y + m.z * wq4.z + m.w * wq4.w;
        float c = m.x * rq4.x + m.y * rq4.y + m.z * rq4.z + m.w * rq4.w;
#pragma unroll
        for (int o = 16; o; o >>= 1) {
            a += __shfl_xor_sync(0xffffffffu, a, o);
            c += __shfl_xor_sync(0xffffffffu, c, o);
        }
        if (lane == 0) { o1[r] = a; o2[r] = c; }
    }
}

// ---------------------------------------------------------------------------
// Kernel 3: dual softmax -> c[b,n] = rw_n*(1-ww_n), s[b] = sum rw_n*ww_n
// grid 64, block 256. 32KB smem for ww and rl.
// ---------------------------------------------------------------------------
__device__ __forceinline__ float blockReduce(float v, bool isMax, float* sred) {
    v = isMax ? warpMax(v) : warpSum(v);
    const int w = threadIdx.x >> 5, l = threadIdx.x & 31;
    if (l == 0) sred[w] = v;
    __syncthreads();
    float r = sred[0];
    if (isMax) { for (int i = 1; i < 8; i++) r = fmaxf(r, sred[i]); }
    else       { for (int i = 1; i < 8; i++) r += sred[i]; }
    __syncthreads();
    return r;
}

__global__ void softmax_kernel() {
    const int b = blockIdx.x;
    const int t = threadIdx.x;                // 0..255
    const float* __restrict__ d1 = g_d1 + b * NSLOT;
    const float* __restrict__ d2 = g_d2 + b * NSLOT;
    const float qv = g_qv[b];

    __shared__ float s_ww[NSLOT];
    __shared__ float s_rl[NSLOT];
    __shared__ float sred[8];

    // write softmax: max + normalizer
    float m = -1e30f;
    for (int n = t; n < NSLOT; n += 256) m = fmaxf(m, d1[n]);
    const float m_w = blockReduce(m, true, sred);

    float z = 0.0f;
    for (int n = t; n < NSLOT; n += 256) z += __expf(d1[n] - m_w);
    const float Z_w = blockReduce(z, false, sred);
    const float invZw = 1.0f / Z_w;

    // read logits rl_n = d2 - ww*(d2 - qv), track max
    float mr = -1e30f;
    for (int n = t; n < NSLOT; n += 256) {
        const float ww = __expf(d1[n] - m_w) * invZw;
        const float v2 = d2[n];
        const float rl = v2 - ww * (v2 - qv);
        s_ww[n] = ww;
        s_rl[n] = rl;
        mr = fmaxf(mr, rl);
    }
    __syncthreads();
    const float m_r = blockReduce(mr, true, sred);

    float zr = 0.0f, ss = 0.0f;
    for (int n = t; n < NSLOT; n += 256) {
        const float e = __expf(s_rl[n] - m_r);
        zr += e;
        ss += e * s_ww[n];
    }
    const float Z_r = blockReduce(zr, false, sred);
    const float S   = blockReduce(ss, false, sred);
    const float invZr = 1.0f / Z_r;

    for (int n = t; n < NSLOT; n += 256) {
        const float rw = __expf(s_rl[n] - m_r) * invZr;
        g_c[b * NSLOT + n] = rw * (1.0f - s_ww[n]);
    }
    if (t == 0) g_s[b] = S * invZr;
}

// ---------------------------------------------------------------------------
// Kernel 4 (pass 2 over memory): g_ro[b,:] += sum_n c[b,n] * mem[b,n,:]
// grid 1024 (64 batches x 16 chunks of 256 rows), block 256.
// ---------------------------------------------------------------------------
__global__ void accum_kernel(const float* __restrict__ mem) {
    const int NP = NSLOT / 16;               // 256 rows per chunk
    const int b  = blockIdx.x >> 4;
    const int ch = blockIdx.x & 15;
    const int t = threadIdx.x, lane = t & 31, rg = t >> 5;   // 8 row groups

    const float* __restrict__ c = g_c + b * NSLOT + ch * NP;
    const float4* mb = reinterpret_cast<const float4*>(
        mem + ((size_t)b * NSLOT + ch * NP) * MEM_D);

    float4 acc = make_float4(0.f, 0.f, 0.f, 0.f);
#pragma unroll 4
    for (int n = rg; n < NP; n += 8) {
        const float cv = c[n];
        const float4 m = mb[(size_t)n * 32 + lane];
        acc.x = fmaf(cv, m.x, acc.x);
        acc.y = fmaf(cv, m.y, acc.y);
        acc.z = fmaf(cv, m.z, acc.z);
        acc.w = fmaf(cv, m.w, acc.w);
    }

    __shared__ float4 sa[256];
    sa[t] = acc;
    __syncthreads();
    if (t < 32) {
        float4 s = sa[t];
#pragma unroll
        for (int r = 1; r < 8; r++) {
            const float4 u = sa[r * 32 + t];
            s.x += u.x; s.y += u.y; s.z += u.z; s.w += u.w;
        }
        float* dst = g_ro + b * MEM_D + t * 4;
        atomicAdd(dst + 0, s.x);
        atomicAdd(dst + 1, s.y);
        atomicAdd(dst + 2, s.z);
        atomicAdd(dst + 3, s.w);
    }
}

// ---------------------------------------------------------------------------
// Kernel 5: out[b,o] = b_ro[o] + sum_d (g_ro[b,d] + s[b]*v[b,d]) * W_ro[d,o]
// grid 64, block 256.
// ---------------------------------------------------------------------------
__global__ void out_kernel(const float* __restrict__ Wro,
                           const float* __restrict__ bro,
                           float* __restrict__ out) {
    const int b = blockIdx.x;
    const int t = threadIdx.x;               // 0..255
    __shared__ float sr[MEM_D];
    if (t < MEM_D) sr[t] = g_ro[b * MEM_D + t] + g_s[b] * g_v[b * MEM_D + t];
    __syncthreads();

    float acc = bro[t];
#pragma unroll 8
    for (int d = 0; d < MEM_D; d++)
        acc = fmaf(sr[d], Wro[d * IN_D + t], acc);
    out[b * IN_D + t] = acc;
}

// ---------------------------------------------------------------------------
extern "C" void kernel_launch(void* const* d_in, const int* in_sizes, int n_in,
                              void* d_out, int out_size) {
    const float* x   = (const float*)d_in[0];
    const float* mem = (const float*)d_in[1];
    const float* Ww  = (const float*)d_in[2];
    const float* bw  = (const float*)d_in[3];
    const float* Wq  = (const float*)d_in[4];
    const float* bq  = (const float*)d_in[5];
    const float* Wr  = (const float*)d_in[6];
    const float* br  = (const float*)d_in[7];
    const float* Wro = (const float*)d_in[8];
    const float* bro = (const float*)d_in[9];
    float* out = (float*)d_out;

    proj_kernel<<<BATCH, 128>>>(x, Ww, bw, Wq, bq, Wr, br);
    dots_kernel<<<1024, 256>>>(mem);
    softmax_kernel<<<BATCH, 256>>>();
    accum_kernel<<<1024, 256>>>(mem);
    out_kernel<<<BATCH, 256>>>(Wro, bro, out);
}